// round 8
// baseline (speedup 1.0000x reference)
#include <cuda_runtime.h>
#include <cuda_fp16.h>
#include <math.h>

#define Bn 4
#define Hn 1080
#define Wn 1920
#define HWn (Hn * Wn)   // 2073600

// ---------------- scratch (no runtime allocation allowed) ----------------
__device__ __align__(16) __half2 g_dc [Bn * HWn];   // (sqrt-diff, color-diff) fp16
__device__ __align__(16) float   g_gt [Bn * HWn];   // tgt gray fp32
__device__ __align__(16) __half2 g_hrt[Bn * HWn];   // (hsum7_ref, hsum7_tgt) fp16
__device__ int   g_maxd_i;
__device__ int   g_maxcd_i;
__device__ float g_sum[Bn];
__device__ float g_invd, g_invcd;

static __forceinline__ __device__ unsigned h2u(__half2 h) {
    return *reinterpret_cast<unsigned*>(&h);
}

// ---------------- K0: zero reduction scalars ------------------------------
__global__ void k0_init() {
    int t = threadIdx.x;
    if (t == 0) g_maxd_i = 0;
    if (t == 1) g_maxcd_i = 0;
    if (t >= 2 && t < 2 + Bn) g_sum[t - 2] = 0.f;
}

// ---------------- K1: one row per block; pointwise + horizontal 7-sums ---
__global__ __launch_bounds__(480) void k1_point(const float* __restrict__ ref,
                                                const float* __restrict__ tgt) {
    const int y = blockIdx.x;
    const int b = blockIdx.y;
    const int t = threadIdx.x;           // 0..479

    __shared__ __align__(16) float srow_r[1928];   // 4 zero pad each side
    __shared__ __align__(16) float srow_t[1928];
    __shared__ float smx[15], smc[15], sms[15];

    if (t < 4) {
        srow_r[t] = 0.f; srow_t[t] = 0.f;
        srow_r[1924 + t] = 0.f; srow_t[1924 + t] = 0.f;
    }

    const size_t rowpx = (size_t)y * Wn + 4 * t;
    const int v = (int)(rowpx >> 2);

    const float4 r0 = ((const float4*)(ref + (size_t)(b * 3 + 0) * HWn))[v];
    const float4 r1 = ((const float4*)(ref + (size_t)(b * 3 + 1) * HWn))[v];
    const float4 r2 = ((const float4*)(ref + (size_t)(b * 3 + 2) * HWn))[v];
    const float4 t0 = ((const float4*)(tgt + (size_t)(b * 3 + 0) * HWn))[v];
    const float4 t1 = ((const float4*)(tgt + (size_t)(b * 3 + 1) * HWn))[v];
    const float4 t2 = ((const float4*)(tgt + (size_t)(b * 3 + 2) * HWn))[v];

    float4 D, C, GR, GT;
    float lmaxd = 0.f, lmaxcd = 0.f, lsum = 0.f;

#define LANE(c)                                                               \
    {                                                                         \
        float d0 = r0.c - t0.c, d1 = r1.c - t1.c, d2 = r2.c - t2.c;           \
        float df = sqrtf(d0 * d0 + d1 * d1 + d2 * d2);                        \
        float cd = (fabsf(d0) + fabsf(d1) + fabsf(d2)) * (1.f / 3.f);         \
        D.c = df; C.c = cd;                                                   \
        GR.c = 0.299f * r0.c + 0.587f * r1.c + 0.114f * r2.c;                 \
        GT.c = 0.299f * t0.c + 0.587f * t1.c + 0.114f * t2.c;                 \
        lmaxd = fmaxf(lmaxd, df); lmaxcd = fmaxf(lmaxcd, cd);                 \
        lsum += df;                                                           \
    }
    LANE(x) LANE(y) LANE(z) LANE(w)
#undef LANE

    uint4 dc;
    dc.x = h2u(__floats2half2_rn(D.x, C.x));
    dc.y = h2u(__floats2half2_rn(D.y, C.y));
    dc.z = h2u(__floats2half2_rn(D.z, C.z));
    dc.w = h2u(__floats2half2_rn(D.w, C.w));
    ((uint4*)(g_dc + (size_t)b * HWn))[v] = dc;
    ((float4*)(g_gt + (size_t)b * HWn))[v] = GT;

    *(float4*)&srow_r[4 + 4 * t] = GR;
    *(float4*)&srow_t[4 + 4 * t] = GT;

    #pragma unroll
    for (int o = 16; o > 0; o >>= 1) {
        lmaxd  = fmaxf(lmaxd,  __shfl_xor_sync(0xffffffffu, lmaxd,  o));
        lmaxcd = fmaxf(lmaxcd, __shfl_xor_sync(0xffffffffu, lmaxcd, o));
        lsum  +=               __shfl_xor_sync(0xffffffffu, lsum,   o);
    }
    const int lane = t & 31, wid = t >> 5;
    if (lane == 0) { smx[wid] = lmaxd; smc[wid] = lmaxcd; sms[wid] = lsum; }
    __syncthreads();
    if (t == 0) {
        float mx = smx[0], mc = smc[0], s = sms[0];
        #pragma unroll
        for (int i = 1; i < 15; i++) {
            mx = fmaxf(mx, smx[i]); mc = fmaxf(mc, smc[i]); s += sms[i];
        }
        atomicMax(&g_maxd_i,  __float_as_int(mx));
        atomicMax(&g_maxcd_i, __float_as_int(mc));
        atomicAdd(&g_sum[b], s);
    }

    const float* ar = srow_r + 4 * t;
    const float* at = srow_t + 4 * t;
    float4 A0 = *(const float4*)(ar), A1 = *(const float4*)(ar + 4), A2 = *(const float4*)(ar + 8);
    float4 B0 = *(const float4*)(at), B1 = *(const float4*)(at + 4), B2 = *(const float4*)(at + 8);
    float a[12] = {A0.x,A0.y,A0.z,A0.w, A1.x,A1.y,A1.z,A1.w, A2.x,A2.y,A2.z,A2.w};
    float c[12] = {B0.x,B0.y,B0.z,B0.w, B1.x,B1.y,B1.z,B1.w, B2.x,B2.y,B2.z,B2.w};

    float hr0 = a[1]+a[2]+a[3]+a[4]+a[5]+a[6]+a[7];
    float ht0 = c[1]+c[2]+c[3]+c[4]+c[5]+c[6]+c[7];
    float hr1 = hr0 + a[8] - a[1], ht1 = ht0 + c[8] - c[1];
    float hr2 = hr1 + a[9] - a[2], ht2 = ht1 + c[9] - c[2];
    float hr3 = hr2 + a[10] - a[3], ht3 = ht2 + c[10] - c[3];

    uint4 hq;
    hq.x = h2u(__floats2half2_rn(hr0, ht0));
    hq.y = h2u(__floats2half2_rn(hr1, ht1));
    hq.z = h2u(__floats2half2_rn(hr2, ht2));
    hq.w = h2u(__floats2half2_rn(hr3, ht3));
    ((uint4*)(g_hrt + (size_t)b * HWn))[v] = hq;
}

// ---------------- K2: score + inverse normalizers ------------------------
__global__ void k2_score(float* __restrict__ out) {
    const int t = threadIdx.x;
    const float invd  = 1.f / (__int_as_float(g_maxd_i)  + 1e-12f);
    const float invcd = 1.f / (__int_as_float(g_maxcd_i) + 1e-12f);
    if (t == 0) { g_invd = invd; g_invcd = invcd; }
    if (t < Bn) {
        float m = g_sum[t] * (1.f / (float)HWn) * invd;
        out[t] = fminf(fmaxf(1.f - m, 0.f), 1.f);
    }
}

// ---------------- K3: warp-strip register kernel (NO shared memory) -------
// Each warp: 64-wide x 16-row strip. Gray neighbors via shuffles; edge and
// blocking bits via ballots; dilation via 64+32-bit mask shift/OR + 5-row
// mask ring. 30 strips x 68 chunks x 4 batches = 8160 warps = 1020 blocks.
struct Row { float l0,c0,r0, l1,c1,r1, l2,c2,r2; };

__global__ __launch_bounds__(256) void k3_stencil(float* __restrict__ diag) {
    const int lane  = threadIdx.x & 31;
    const int wtask = blockIdx.x * 8 + (threadIdx.x >> 5);
    const int b     = wtask / 2040;
    const int r2i   = wtask - b * 2040;
    const int chunk = r2i / 30;
    const int strip = r2i - chunk * 30;
    const int x0    = strip * 64;
    const int yB    = chunk * 16;

    const float*   gtb = g_gt  + (size_t)b * HWn;
    const __half2* hqb = g_hrt + (size_t)b * HWn;
    const __half2* dcp = g_dc  + (size_t)b * HWn;
    float* o_an = diag + ((size_t)b * 5 + 0) * HWn;
    float* o_cm = diag + ((size_t)b * 5 + 1) * HWn;
    float* o_ss = diag + ((size_t)b * 5 + 2) * HWn;
    float* o_bl = diag + ((size_t)b * 5 + 3) * HWn;
    float* o_ri = diag + ((size_t)b * 5 + 4) * HWn;

    const int colL = x0 - 4 + lane;    // gray/edge col, group 0 (left halo)
    const int colM = x0 + 28 + lane;   // group 1
    const int colR = x0 + 60 + lane;   // group 2 (right halo)
    const int ca   = x0 + lane;        // output col a
    const int cb   = x0 + 32 + lane;   // output col b
    const bool vL = (colL >= 0) && (colL < Wn);
    const bool vR = (colR < Wn);
    const bool cm8L = ((colL & 7) == 0);
    const bool cm8M = ((colM & 7) == 0);
    const bool cm8R = ((colR & 7) == 0);

    // gray row with shuffle-built left/right neighbors (zero-padded bounds)
    auto load_row = [&](int y) -> Row {
        const bool rv = ((unsigned)y < (unsigned)Hn);
        const float* rp = gtb + (size_t)y * Wn;
        float n0 = (rv && vL) ? __ldg(rp + colL) : 0.f;
        float n1 = rv          ? __ldg(rp + colM) : 0.f;
        float n2 = (rv && vR) ? __ldg(rp + colR) : 0.f;
        Row t;
        t.c0 = n0; t.c1 = n1; t.c2 = n2;
        float u0 = __shfl_up_sync(0xffffffffu, n0, 1);
        float u1 = __shfl_up_sync(0xffffffffu, n1, 1);
        float u2 = __shfl_up_sync(0xffffffffu, n2, 1);
        float p0 = __shfl_sync(0xffffffffu, n0, 31);
        float p1 = __shfl_sync(0xffffffffu, n1, 31);
        if (lane == 0) { u1 = p0; u2 = p1; }   // u0 at lane0: unused bit
        t.l0 = u0; t.l1 = u1; t.l2 = u2;
        float d0 = __shfl_down_sync(0xffffffffu, n0, 1);
        float d1 = __shfl_down_sync(0xffffffffu, n1, 1);
        float d2 = __shfl_down_sync(0xffffffffu, n2, 1);
        float q0 = __shfl_sync(0xffffffffu, n1, 0);
        float q1 = __shfl_sync(0xffffffffu, n2, 0);
        if (lane == 31) { d0 = q0; d1 = q1; }  // d2 at lane31: unused bit
        t.r0 = d0; t.r1 = d1; t.r2 = d2;
        return t;
    };

    auto ldh = [&](int y, int c) -> float2 {
        if ((unsigned)y < (unsigned)Hn)
            return __half22float2(__ldg(hqb + (size_t)y * Wn + c));
        return make_float2(0.f, 0.f);
    };

    // ring state
    Row rA = load_row(yB - 3);   // row e-1
    Row rB = load_row(yB - 2);   // row e

    unsigned long long hdL0=0,hdL1=0,hdL2=0,hdL3=0,hdL4=0;  // hdil lo ring
    unsigned           hdH0=0,hdH1=0,hdH2=0,hdH3=0,hdH4=0;  // hdil hi ring
    unsigned long long emL0=0,emL1=0,emL2=0;                // edge lo ring
    unsigned           emH0=0,emH1=0,emH2=0;                // edge hi ring
    unsigned long long bkL0=0,bkL1=0,bkL2=0;                // blk lo ring
    unsigned           bkH0=0,bkH1=0,bkH2=0;                // blk hi ring

    // edge step: loads gray row e+1, computes edge/blk/hdil masks for row e
    auto edge_step = [&](int e) {
        Row n = load_row(e + 1);
        const bool rowv = ((unsigned)e < (unsigned)Hn);
        const bool r8   = rowv && ((e & 7) == 0);

        float gx0 = (rA.r0 - rA.l0) + 2.f*(rB.r0 - rB.l0) + (n.r0 - n.l0);
        float gy0 = (n.l0 - rA.l0) + 2.f*(n.c0 - rA.c0) + (n.r0 - rA.r0);
        float gx1 = (rA.r1 - rA.l1) + 2.f*(rB.r1 - rB.l1) + (n.r1 - n.l1);
        float gy1 = (n.l1 - rA.l1) + 2.f*(n.c1 - rA.c1) + (n.r1 - rA.r1);
        float gx2 = (rA.r2 - rA.l2) + 2.f*(rB.r2 - rB.l2) + (n.r2 - n.l2);
        float gy2 = (n.l2 - rA.l2) + 2.f*(n.c2 - rA.c2) + (n.r2 - rA.r2);

        bool e0 = rowv && vL && (sqrtf(gx0*gx0 + gy0*gy0) > 0.15f);
        bool e1 = rowv &&       (sqrtf(gx1*gx1 + gy1*gy1) > 0.15f);
        bool e2 = rowv && vR && (sqrtf(gx2*gx2 + gy2*gy2) > 0.15f);
        unsigned eb0 = __ballot_sync(0xffffffffu, e0);
        unsigned eb1 = __ballot_sync(0xffffffffu, e1);
        unsigned eb2 = __ballot_sync(0xffffffffu, e2);
        unsigned long long elo = (unsigned long long)eb0 | ((unsigned long long)eb1 << 32);
        unsigned ehi = eb2;

        float bv0 = cm8L ? fabsf(gx0) : 0.f;
        float bv1 = cm8M ? fabsf(gx1) : 0.f;
        float bv2 = cm8R ? fabsf(gx2) : 0.f;
        if (r8) {
            bv0 = fmaxf(bv0, fabsf(gy0));
            bv1 = fmaxf(bv1, fabsf(gy1));
            bv2 = fmaxf(bv2, fabsf(gy2));
        }
        bool b0 = rowv && vL && (bv0 > 0.05f);
        bool b1 = rowv &&       (bv1 > 0.05f);
        bool b2 = rowv && vR && (bv2 > 0.05f);
        unsigned bb0 = __ballot_sync(0xffffffffu, b0);
        unsigned bb1 = __ballot_sync(0xffffffffu, b1);
        unsigned bb2 = __ballot_sync(0xffffffffu, b2);
        unsigned long long blo = (unsigned long long)bb0 | ((unsigned long long)bb1 << 32);
        unsigned bhi = bb2;

        // horizontal 5-wide dilation of edge mask (96-bit virtual word)
        unsigned long long dl = elo | (elo << 1) | (elo << 2) | (elo >> 1) | (elo >> 2)
                              | ((unsigned long long)ehi << 63)
                              | ((unsigned long long)ehi << 62);
        unsigned dh = ehi | (ehi << 1) | (ehi << 2) | (ehi >> 1) | (ehi >> 2)
                    | (unsigned)(elo >> 63) | (unsigned)(elo >> 62);

        hdL0=hdL1; hdL1=hdL2; hdL2=hdL3; hdL3=hdL4; hdL4=dl;
        hdH0=hdH1; hdH1=hdH2; hdH2=hdH3; hdH3=hdH4; hdH4=dh;
        emL0=emL1; emL1=emL2; emL2=elo;
        emH0=emH1; emH1=emH2; emH2=ehi;
        bkL0=bkL1; bkL1=bkL2; bkL2=blo;
        bkH0=bkH1; bkH1=bkH2; bkH2=bhi;
        rA = rB; rB = n;
    };

    // warm-up: edges for rows yB-2..yB+1
    edge_step(yB - 2);
    edge_step(yB - 1);
    edge_step(yB);
    edge_step(yB + 1);

    // warm-up: box vertical sums = window of row yB-1 (rows yB-4..yB+2),
    // so the first slide (add yB+3, sub yB-4) yields the window of row yB.
    float sRa = 0.f, sTa = 0.f, sRb = 0.f, sTb = 0.f;
    #pragma unroll
    for (int k = -4; k <= 2; k++) {
        float2 ha = ldh(yB + k, ca);
        float2 hb = ldh(yB + k, cb);
        sRa += ha.x; sTa += ha.y;
        sRb += hb.x; sTb += hb.y;
    }

    const float invd  = g_invd;
    const float invcd = g_invcd;

    for (int t = 0; t < 16; t++) {
        const int y = yB + t;
        if (y >= Hn) break;

        edge_step(y + 2);   // rings now hold rows y-2..y+2 (hd), y..y+2 (em/bk)

        float2 ha = ldh(y + 3, ca), hb = ldh(y + 3, cb);
        float2 oa = ldh(y - 4, ca), ob = ldh(y - 4, cb);
        sRa += ha.x - oa.x; sTa += ha.y - oa.y;
        sRb += hb.x - ob.x; sTb += hb.y - ob.y;

        const unsigned long long dlo = hdL0 | hdL1 | hdL2 | hdL3 | hdL4;
        const unsigned           dhi = hdH0 | hdH1 | hdH2 | hdH3 | hdH4;

        // col a: bit lane+4 of lo words
        const int pa = lane + 4;
        float dila = (float)((dlo  >> pa) & 1ull);
        float ea   = (float)((emL0 >> pa) & 1ull);
        float bka  = (float)((bkL0 >> pa) & 1ull);
        // col b: lanes 0..27 -> lo bit lane+36; lanes 28..31 -> hi bit lane-28
        unsigned long long sdil = (lane < 28) ? (dlo  >> (lane + 36)) : (unsigned long long)(dhi  >> (lane - 28));
        unsigned long long sem  = (lane < 28) ? (emL0 >> (lane + 36)) : (unsigned long long)(emH0 >> (lane - 28));
        unsigned long long sbk  = (lane < 28) ? (bkL0 >> (lane + 36)) : (unsigned long long)(bkH0 >> (lane - 28));
        float dilb = (float)(sdil & 1ull);
        float eb   = (float)(sem  & 1ull);
        float bkb  = (float)(sbk  & 1ull);

        const __half2* dr = dcp + (size_t)y * Wn;
        float2 da = __half22float2(__ldg(dr + ca));
        float2 db = __half22float2(__ldg(dr + cb));
        float ana = da.x * invd, cma = da.y * invcd;
        float anb = db.x * invd, cmb = db.y * invcd;

        float mu_ra = sRa * (1.f / 49.f), mu_ta = sTa * (1.f / 49.f);
        float mu_rb = sRb * (1.f / 49.f), mu_tb = sTb * (1.f / 49.f);
        float ssa = (2.f * mu_ra * mu_ta + 1e-4f) / (mu_ra * mu_ra + mu_ta * mu_ta + 1e-4f);
        float ssb = (2.f * mu_rb * mu_tb + 1e-4f) / (mu_rb * mu_rb + mu_tb * mu_tb + 1e-4f);

        float ringa = fmaxf(dila - ea, 0.f) * ana;
        float ringb = fmaxf(dilb - eb, 0.f) * anb;

        const size_t ia = (size_t)y * Wn + ca;
        const size_t ib = ia + 32;
        o_an[ia] = ana;  o_an[ib] = anb;
        o_cm[ia] = cma;  o_cm[ib] = cmb;
        o_ss[ia] = ssa;  o_ss[ib] = ssb;
        o_bl[ia] = bka;  o_bl[ib] = bkb;
        o_ri[ia] = ringa; o_ri[ib] = ringb;
    }
}

// ---------------- launch ---------------------------------------------------
extern "C" void kernel_launch(void* const* d_in, const int* in_sizes, int n_in,
                              void* d_out, int out_size) {
    const float* ref = (const float*)d_in[0];
    const float* tgt = (const float*)d_in[1];
    float* out = (float*)d_out;

    k0_init<<<1, 32>>>();

    dim3 g1(Hn, Bn);
    k1_point<<<g1, 480>>>(ref, tgt);

    k2_score<<<1, 32>>>(out);

    // 30 strips x 68 chunks x 4 batches = 8160 warp-tasks = 1020 blocks
    k3_stencil<<<1020, 256>>>(out + Bn);
}

// round 9
// speedup vs baseline: 1.8089x; 1.8089x over previous
#include <cuda_runtime.h>
#include <cuda_fp16.h>
#include <math.h>

#define Bn 4
#define Hn 1080
#define Wn 1920
#define HWn (Hn * Wn)   // 2073600
#define NSPAN 60        // 1920 / 32
#define NWRD  (Hn * NSPAN)

// ---------------- scratch (no runtime allocation allowed) ----------------
__device__ __align__(16) __half2 g_dc [Bn * HWn];   // (sqrt-diff, color-diff) fp16
__device__ __align__(16) float   g_gt [Bn * HWn];   // tgt gray fp32
__device__ __align__(16) __half2 g_hrt[Bn * HWn];   // (hsum7_ref, hsum7_tgt) fp16
__device__ __align__(16) unsigned g_edgew[Bn * NWRD];  // edge bits, 1/px
__device__ __align__(16) unsigned g_blkw [Bn * NWRD];  // blocking bits, 1/px
__device__ int   g_maxd_i;
__device__ int   g_maxcd_i;
__device__ float g_sum[Bn];
__device__ float g_invd, g_invcd;

static __forceinline__ __device__ unsigned h2u(__half2 h) {
    return *reinterpret_cast<unsigned*>(&h);
}

// ---------------- K0: zero reduction scalars ------------------------------
__global__ void k0_init() {
    int t = threadIdx.x;
    if (t == 0) g_maxd_i = 0;
    if (t == 1) g_maxcd_i = 0;
    if (t >= 2 && t < 2 + Bn) g_sum[t - 2] = 0.f;
}

// ---------------- K1: one row per block; pointwise + horizontal 7-sums ---
__global__ __launch_bounds__(480) void k1_point(const float* __restrict__ ref,
                                                const float* __restrict__ tgt) {
    const int y = blockIdx.x;
    const int b = blockIdx.y;
    const int t = threadIdx.x;           // 0..479

    __shared__ __align__(16) float srow_r[1928];   // 4 zero pad each side
    __shared__ __align__(16) float srow_t[1928];
    __shared__ float smx[15], smc[15], sms[15];

    if (t < 4) {
        srow_r[t] = 0.f; srow_t[t] = 0.f;
        srow_r[1924 + t] = 0.f; srow_t[1924 + t] = 0.f;
    }

    const size_t rowpx = (size_t)y * Wn + 4 * t;
    const int v = (int)(rowpx >> 2);

    const float4 r0 = ((const float4*)(ref + (size_t)(b * 3 + 0) * HWn))[v];
    const float4 r1 = ((const float4*)(ref + (size_t)(b * 3 + 1) * HWn))[v];
    const float4 r2 = ((const float4*)(ref + (size_t)(b * 3 + 2) * HWn))[v];
    const float4 t0 = ((const float4*)(tgt + (size_t)(b * 3 + 0) * HWn))[v];
    const float4 t1 = ((const float4*)(tgt + (size_t)(b * 3 + 1) * HWn))[v];
    const float4 t2 = ((const float4*)(tgt + (size_t)(b * 3 + 2) * HWn))[v];

    float4 D, C, GR, GT;
    float lmaxd = 0.f, lmaxcd = 0.f, lsum = 0.f;

#define LANE(c)                                                               \
    {                                                                         \
        float d0 = r0.c - t0.c, d1 = r1.c - t1.c, d2 = r2.c - t2.c;           \
        float df = sqrtf(d0 * d0 + d1 * d1 + d2 * d2);                        \
        float cd = (fabsf(d0) + fabsf(d1) + fabsf(d2)) * (1.f / 3.f);         \
        D.c = df; C.c = cd;                                                   \
        GR.c = 0.299f * r0.c + 0.587f * r1.c + 0.114f * r2.c;                 \
        GT.c = 0.299f * t0.c + 0.587f * t1.c + 0.114f * t2.c;                 \
        lmaxd = fmaxf(lmaxd, df); lmaxcd = fmaxf(lmaxcd, cd);                 \
        lsum += df;                                                           \
    }
    LANE(x) LANE(y) LANE(z) LANE(w)
#undef LANE

    uint4 dc;
    dc.x = h2u(__floats2half2_rn(D.x, C.x));
    dc.y = h2u(__floats2half2_rn(D.y, C.y));
    dc.z = h2u(__floats2half2_rn(D.z, C.z));
    dc.w = h2u(__floats2half2_rn(D.w, C.w));
    ((uint4*)(g_dc + (size_t)b * HWn))[v] = dc;
    ((float4*)(g_gt + (size_t)b * HWn))[v] = GT;

    *(float4*)&srow_r[4 + 4 * t] = GR;
    *(float4*)&srow_t[4 + 4 * t] = GT;

    #pragma unroll
    for (int o = 16; o > 0; o >>= 1) {
        lmaxd  = fmaxf(lmaxd,  __shfl_xor_sync(0xffffffffu, lmaxd,  o));
        lmaxcd = fmaxf(lmaxcd, __shfl_xor_sync(0xffffffffu, lmaxcd, o));
        lsum  +=               __shfl_xor_sync(0xffffffffu, lsum,   o);
    }
    const int lane = t & 31, wid = t >> 5;
    if (lane == 0) { smx[wid] = lmaxd; smc[wid] = lmaxcd; sms[wid] = lsum; }
    __syncthreads();
    if (t == 0) {
        float mx = smx[0], mc = smc[0], s = sms[0];
        #pragma unroll
        for (int i = 1; i < 15; i++) {
            mx = fmaxf(mx, smx[i]); mc = fmaxf(mc, smc[i]); s += sms[i];
        }
        atomicMax(&g_maxd_i,  __float_as_int(mx));
        atomicMax(&g_maxcd_i, __float_as_int(mc));
        atomicAdd(&g_sum[b], s);
    }

    const float* ar = srow_r + 4 * t;
    const float* at = srow_t + 4 * t;
    float4 A0 = *(const float4*)(ar), A1 = *(const float4*)(ar + 4), A2 = *(const float4*)(ar + 8);
    float4 B0 = *(const float4*)(at), B1 = *(const float4*)(at + 4), B2 = *(const float4*)(at + 8);
    float a[12] = {A0.x,A0.y,A0.z,A0.w, A1.x,A1.y,A1.z,A1.w, A2.x,A2.y,A2.z,A2.w};
    float c[12] = {B0.x,B0.y,B0.z,B0.w, B1.x,B1.y,B1.z,B1.w, B2.x,B2.y,B2.z,B2.w};

    float hr0 = a[1]+a[2]+a[3]+a[4]+a[5]+a[6]+a[7];
    float ht0 = c[1]+c[2]+c[3]+c[4]+c[5]+c[6]+c[7];
    float hr1 = hr0 + a[8] - a[1], ht1 = ht0 + c[8] - c[1];
    float hr2 = hr1 + a[9] - a[2], ht2 = ht1 + c[9] - c[2];
    float hr3 = hr2 + a[10] - a[3], ht3 = ht2 + c[10] - c[3];

    uint4 hq;
    hq.x = h2u(__floats2half2_rn(hr0, ht0));
    hq.y = h2u(__floats2half2_rn(hr1, ht1));
    hq.z = h2u(__floats2half2_rn(hr2, ht2));
    hq.w = h2u(__floats2half2_rn(hr3, ht3));
    ((uint4*)(g_hrt + (size_t)b * HWn))[v] = hq;
}

// ---------------- K2: score + inverse normalizers ------------------------
__global__ void k2_score(float* __restrict__ out) {
    const int t = threadIdx.x;
    const float invd  = 1.f / (__int_as_float(g_maxd_i)  + 1e-12f);
    const float invcd = 1.f / (__int_as_float(g_maxcd_i) + 1e-12f);
    if (t == 0) { g_invd = invd; g_invcd = invcd; }
    if (t < Bn) {
        float m = g_sum[t] * (1.f / (float)HWn) * invd;
        out[t] = fminf(fmaxf(1.f - m, 0.f), 1.f);
    }
}

// ---------------- K2b: Sobel -> edge/blocking bit-words --------------------
// Warp = 32-col span x 8 rows (sliding). 60 spans x 135 chunks x 4 = 32400
// warps = 4050 blocks. All arithmetic identical to prior (passing) Sobel.
struct R3r { float l, c, r; };

__global__ __launch_bounds__(256) void k2b_edge() {
    const int lane = threadIdx.x & 31;
    const int task = blockIdx.x * 8 + (threadIdx.x >> 5);
    const int s    = task % NSPAN;
    const int rem  = task / NSPAN;
    const int chnk = rem % 135;
    const int b    = rem / 135;
    const int yB   = chnk * 8;
    const int c    = s * 32 + lane;

    const float* gtb = g_gt + (size_t)b * HWn;
    unsigned* ew = g_edgew + (size_t)b * NWRD;
    unsigned* bw = g_blkw  + (size_t)b * NWRD;

    auto loadrow = [&](int y) -> R3r {
        R3r t;
        const bool rv = ((unsigned)y < (unsigned)Hn);
        float ctr = rv ? __ldg(gtb + (size_t)y * Wn + c) : 0.f;
        t.c = ctr;
        float lf = __shfl_up_sync(0xffffffffu, ctr, 1);
        if (lane == 0)  lf = (rv && c > 0) ? __ldg(gtb + (size_t)y * Wn + c - 1) : 0.f;
        float rt = __shfl_down_sync(0xffffffffu, ctr, 1);
        if (lane == 31) rt = (rv && c + 1 < Wn) ? __ldg(gtb + (size_t)y * Wn + c + 1) : 0.f;
        t.l = lf; t.r = rt;
        return t;
    };

    R3r rA = loadrow(yB - 1);
    R3r rB = loadrow(yB);

    #pragma unroll
    for (int t = 0; t < 8; t++) {
        const int y = yB + t;
        R3r n = loadrow(y + 1);
        float gx = (rA.r - rA.l) + 2.f * (rB.r - rB.l) + (n.r - n.l);
        float gy = (n.l - rA.l) + 2.f * (n.c - rA.c) + (n.r - rA.r);

        bool edge = sqrtf(gx * gx + gy * gy) > 0.15f;
        float bv = ((lane & 7) == 0) ? fabsf(gx) : 0.f;
        if ((y & 7) == 0) bv = fmaxf(bv, fabsf(gy));
        bool blk = bv > 0.05f;

        unsigned eb = __ballot_sync(0xffffffffu, edge);
        unsigned bb = __ballot_sync(0xffffffffu, blk);
        if (lane == 0) {
            ew[y * NSPAN + s] = eb;
            bw[y * NSPAN + s] = bb;
        }
        rA = rB; rB = n;
    }
}

// ---------------- K3: pure streaming output kernel (no smem, no barriers) --
// block (32,8); thread = col gx, rows yb..yb+3. grid (60, 34, 4).
__global__ __launch_bounds__(256) void k3_out(float* __restrict__ diag) {
    const int lane = threadIdx.x;
    const int ty   = threadIdx.y;
    const int s    = blockIdx.x;
    const int b    = blockIdx.z;
    const int yb   = blockIdx.y * 32 + ty * 4;
    const int gx   = s * 32 + lane;

    const __half2* hqb = g_hrt + (size_t)b * HWn;
    const __half2* dcp = g_dc  + (size_t)b * HWn;
    const unsigned* ew = g_edgew + (size_t)b * NWRD;
    const unsigned* bw = g_blkw  + (size_t)b * NWRD;
    float* o_an = diag + ((size_t)b * 5 + 0) * HWn;
    float* o_cm = diag + ((size_t)b * 5 + 1) * HWn;
    float* o_ss = diag + ((size_t)b * 5 + 2) * HWn;
    float* o_bl = diag + ((size_t)b * 5 + 3) * HWn;
    float* o_ri = diag + ((size_t)b * 5 + 4) * HWn;

    // ---- hrt vertical windows: rows yb-3 .. yb+6 ----
    float2 h[10];
    #pragma unroll
    for (int k = 0; k < 10; k++) {
        int y = yb - 3 + k;
        h[k] = ((unsigned)y < (unsigned)Hn)
             ? __half22float2(__ldg(hqb + (size_t)y * Wn + gx))
             : make_float2(0.f, 0.f);
    }
    float mur[4], mut[4];
    #pragma unroll
    for (int q = 0; q < 4; q++) {
        float sr = 0.f, st = 0.f;
        #pragma unroll
        for (int k = 0; k < 7; k++) { sr += h[q + k].x; st += h[q + k].y; }
        mur[q] = sr; mut[q] = st;
    }

    // ---- dc for the 4 output pixels ----
    __half2 pdc[4];
    #pragma unroll
    for (int r = 0; r < 4; r++) {
        int y = yb + r;
        pdc[r] = (y < Hn) ? __ldg(dcp + (size_t)y * Wn + gx) : __half2(__float2half2_rn(0.f));
    }

    // ---- gather mask words via lane-split load + shuffles ----
    // lanes 0-7: edge cur rows yb-2..yb+5 | 8-15: edge prev-span | 16-23: edge
    // next-span | 24-27: blk rows yb..yb+3
    unsigned v = 0u;
    {
        const int r = lane & 7;
        const int row = yb - 2 + r;
        const bool okr = ((unsigned)row < (unsigned)Hn);
        if (lane < 8) {
            if (okr) v = __ldg(ew + row * NSPAN + s);
        } else if (lane < 16) {
            if (okr && s > 0) v = __ldg(ew + row * NSPAN + s - 1);
        } else if (lane < 24) {
            if (okr && s < NSPAN - 1) v = __ldg(ew + row * NSPAN + s + 1);
        } else {
            const int q = lane - 24;
            const int row2 = yb + q;
            if (q < 4 && row2 < Hn) v = __ldg(bw + row2 * NSPAN + s);
        }
    }
    unsigned ec[8], hd[8], bkw[4];
    #pragma unroll
    for (int r = 0; r < 8; r++) {
        unsigned cw = __shfl_sync(0xffffffffu, v, r);
        unsigned pw = __shfl_sync(0xffffffffu, v, 8 + r);
        unsigned nw = __shfl_sync(0xffffffffu, v, 16 + r);
        ec[r] = cw;
        hd[r] = cw | (cw << 1) | (cw << 2) | (cw >> 1) | (cw >> 2)
              | (pw >> 30) | (pw >> 31) | (nw << 30) | (nw << 31);
    }
    #pragma unroll
    for (int q = 0; q < 4; q++) bkw[q] = __shfl_sync(0xffffffffu, v, 24 + q);

    const float invd  = g_invd;
    const float invcd = g_invcd;

    #pragma unroll
    for (int q = 0; q < 4; q++) {
        const int y = yb + q;
        if (y >= Hn) break;

        unsigned dw = hd[q] | hd[q + 1] | hd[q + 2] | hd[q + 3] | hd[q + 4];
        float dil = (float)((dw       >> lane) & 1u);
        float e   = (float)((ec[q + 2] >> lane) & 1u);
        float bk  = (float)((bkw[q]   >> lane) & 1u);

        float mu_r = mur[q] * (1.f / 49.f), mu_t = mut[q] * (1.f / 49.f);
        float ssim = (2.f * mu_r * mu_t + 1e-4f) / (mu_r * mu_r + mu_t * mu_t + 1e-4f);

        float2 dc = __half22float2(pdc[q]);
        float an  = dc.x * invd;
        float cm  = dc.y * invcd;
        float ring = fmaxf(dil - e, 0.f) * an;

        const size_t idx = (size_t)y * Wn + gx;
        o_an[idx] = an;
        o_cm[idx] = cm;
        o_ss[idx] = ssim;
        o_bl[idx] = bk;
        o_ri[idx] = ring;
    }
}

// ---------------- launch ---------------------------------------------------
extern "C" void kernel_launch(void* const* d_in, const int* in_sizes, int n_in,
                              void* d_out, int out_size) {
    const float* ref = (const float*)d_in[0];
    const float* tgt = (const float*)d_in[1];
    float* out = (float*)d_out;

    k0_init<<<1, 32>>>();

    dim3 g1(Hn, Bn);
    k1_point<<<g1, 480>>>(ref, tgt);

    k2_score<<<1, 32>>>(out);

    k2b_edge<<<4050, 256>>>();

    dim3 g3(NSPAN, (Hn + 31) / 32, Bn);
    dim3 b3(32, 8);
    k3_out<<<g3, b3>>>(out + Bn);
}

// round 10
// speedup vs baseline: 2.0222x; 1.1179x over previous
#include <cuda_runtime.h>
#include <cuda_fp16.h>
#include <math.h>

#define Bn 4
#define Hn 1080
#define Wn 1920
#define HWn (Hn * Wn)   // 2073600
#define NSPAN 60        // 1920 / 32 (bit-words per row)
#define NWRD  (Hn * NSPAN)
#define SPN   15        // 1920 / 128 (k2b warp spans)

// ---------------- scratch (no runtime allocation allowed) ----------------
__device__ __align__(16) __half2 g_dc [Bn * HWn];   // (sqrt-diff, color-diff) fp16
__device__ __align__(16) float   g_gt [Bn * HWn];   // tgt gray fp32
__device__ __align__(16) __half2 g_hrt[Bn * HWn];   // (hsum7_ref, hsum7_tgt) fp16
__device__ __align__(16) unsigned g_edgew[Bn * NWRD];  // edge bits, 1/px
__device__ __align__(16) unsigned g_blkw [Bn * NWRD];  // blocking bits, 1/px
__device__ int   g_maxd_i;
__device__ int   g_maxcd_i;
__device__ float g_sum[Bn];
__device__ float g_invd, g_invcd;

static __forceinline__ __device__ unsigned h2u(__half2 h) {
    return *reinterpret_cast<unsigned*>(&h);
}

// ---------------- K0: zero reduction scalars ------------------------------
__global__ void k0_init() {
    int t = threadIdx.x;
    if (t == 0) g_maxd_i = 0;
    if (t == 1) g_maxcd_i = 0;
    if (t >= 2 && t < 2 + Bn) g_sum[t - 2] = 0.f;
}

// ---------------- K1: one row per block; pointwise + horizontal 7-sums ---
__global__ __launch_bounds__(480) void k1_point(const float* __restrict__ ref,
                                                const float* __restrict__ tgt) {
    const int y = blockIdx.x;
    const int b = blockIdx.y;
    const int t = threadIdx.x;           // 0..479

    __shared__ __align__(16) float srow_r[1928];   // 4 zero pad each side
    __shared__ __align__(16) float srow_t[1928];
    __shared__ float smx[15], smc[15], sms[15];

    if (t < 4) {
        srow_r[t] = 0.f; srow_t[t] = 0.f;
        srow_r[1924 + t] = 0.f; srow_t[1924 + t] = 0.f;
    }

    const size_t rowpx = (size_t)y * Wn + 4 * t;
    const int v = (int)(rowpx >> 2);

    const float4 r0 = ((const float4*)(ref + (size_t)(b * 3 + 0) * HWn))[v];
    const float4 r1 = ((const float4*)(ref + (size_t)(b * 3 + 1) * HWn))[v];
    const float4 r2 = ((const float4*)(ref + (size_t)(b * 3 + 2) * HWn))[v];
    const float4 t0 = ((const float4*)(tgt + (size_t)(b * 3 + 0) * HWn))[v];
    const float4 t1 = ((const float4*)(tgt + (size_t)(b * 3 + 1) * HWn))[v];
    const float4 t2 = ((const float4*)(tgt + (size_t)(b * 3 + 2) * HWn))[v];

    float4 D, C, GR, GT;
    float lmaxd = 0.f, lmaxcd = 0.f, lsum = 0.f;

#define LANE(c)                                                               \
    {                                                                         \
        float d0 = r0.c - t0.c, d1 = r1.c - t1.c, d2 = r2.c - t2.c;           \
        float df = sqrtf(d0 * d0 + d1 * d1 + d2 * d2);                        \
        float cd = (fabsf(d0) + fabsf(d1) + fabsf(d2)) * (1.f / 3.f);         \
        D.c = df; C.c = cd;                                                   \
        GR.c = 0.299f * r0.c + 0.587f * r1.c + 0.114f * r2.c;                 \
        GT.c = 0.299f * t0.c + 0.587f * t1.c + 0.114f * t2.c;                 \
        lmaxd = fmaxf(lmaxd, df); lmaxcd = fmaxf(lmaxcd, cd);                 \
        lsum += df;                                                           \
    }
    LANE(x) LANE(y) LANE(z) LANE(w)
#undef LANE

    uint4 dc;
    dc.x = h2u(__floats2half2_rn(D.x, C.x));
    dc.y = h2u(__floats2half2_rn(D.y, C.y));
    dc.z = h2u(__floats2half2_rn(D.z, C.z));
    dc.w = h2u(__floats2half2_rn(D.w, C.w));
    ((uint4*)(g_dc + (size_t)b * HWn))[v] = dc;
    ((float4*)(g_gt + (size_t)b * HWn))[v] = GT;

    *(float4*)&srow_r[4 + 4 * t] = GR;
    *(float4*)&srow_t[4 + 4 * t] = GT;

    #pragma unroll
    for (int o = 16; o > 0; o >>= 1) {
        lmaxd  = fmaxf(lmaxd,  __shfl_xor_sync(0xffffffffu, lmaxd,  o));
        lmaxcd = fmaxf(lmaxcd, __shfl_xor_sync(0xffffffffu, lmaxcd, o));
        lsum  +=               __shfl_xor_sync(0xffffffffu, lsum,   o);
    }
    const int lane = t & 31, wid = t >> 5;
    if (lane == 0) { smx[wid] = lmaxd; smc[wid] = lmaxcd; sms[wid] = lsum; }
    __syncthreads();
    if (t == 0) {
        float mx = smx[0], mc = smc[0], s = sms[0];
        #pragma unroll
        for (int i = 1; i < 15; i++) {
            mx = fmaxf(mx, smx[i]); mc = fmaxf(mc, smc[i]); s += sms[i];
        }
        atomicMax(&g_maxd_i,  __float_as_int(mx));
        atomicMax(&g_maxcd_i, __float_as_int(mc));
        atomicAdd(&g_sum[b], s);
    }

    const float* ar = srow_r + 4 * t;
    const float* at = srow_t + 4 * t;
    float4 A0 = *(const float4*)(ar), A1 = *(const float4*)(ar + 4), A2 = *(const float4*)(ar + 8);
    float4 B0 = *(const float4*)(at), B1 = *(const float4*)(at + 4), B2 = *(const float4*)(at + 8);
    float a[12] = {A0.x,A0.y,A0.z,A0.w, A1.x,A1.y,A1.z,A1.w, A2.x,A2.y,A2.z,A2.w};
    float c[12] = {B0.x,B0.y,B0.z,B0.w, B1.x,B1.y,B1.z,B1.w, B2.x,B2.y,B2.z,B2.w};

    float hr0 = a[1]+a[2]+a[3]+a[4]+a[5]+a[6]+a[7];
    float ht0 = c[1]+c[2]+c[3]+c[4]+c[5]+c[6]+c[7];
    float hr1 = hr0 + a[8] - a[1], ht1 = ht0 + c[8] - c[1];
    float hr2 = hr1 + a[9] - a[2], ht2 = ht1 + c[9] - c[2];
    float hr3 = hr2 + a[10] - a[3], ht3 = ht2 + c[10] - c[3];

    uint4 hq;
    hq.x = h2u(__floats2half2_rn(hr0, ht0));
    hq.y = h2u(__floats2half2_rn(hr1, ht1));
    hq.z = h2u(__floats2half2_rn(hr2, ht2));
    hq.w = h2u(__floats2half2_rn(hr3, ht3));
    ((uint4*)(g_hrt + (size_t)b * HWn))[v] = hq;
}

// ---------------- K2: score + inverse normalizers ------------------------
__global__ void k2_score(float* __restrict__ out) {
    const int t = threadIdx.x;
    const float invd  = 1.f / (__int_as_float(g_maxd_i)  + 1e-12f);
    const float invcd = 1.f / (__int_as_float(g_maxcd_i) + 1e-12f);
    if (t == 0) { g_invd = invd; g_invcd = invcd; }
    if (t < Bn) {
        float m = g_sum[t] * (1.f / (float)HWn) * invd;
        out[t] = fminf(fmaxf(1.f - m, 0.f), 1.f);
    }
}

// ---------------- K2b: vectorized Sobel -> edge/blocking bit-words ---------
// Warp = 128-col span (float4 per thread) x 8 rows sliding. Nibble packing +
// 3 shfl_xor-OR steps replace ballots. 15 spans x 135 chunks x 4 = 8100 warps.
struct R6v { float v[6]; };   // [l, x, y, z, w, r]

__global__ __launch_bounds__(256) void k2b_edge() {
    const int lane = threadIdx.x & 31;
    const int task = blockIdx.x * 8 + (threadIdx.x >> 5);
    if (task >= SPN * 135 * Bn) return;
    const int s    = task % SPN;
    const int rem  = task / SPN;
    const int chnk = rem % 135;
    const int b    = rem / 135;
    const int yB   = chnk * 8;
    const int x0v  = s * 128 + lane * 4;

    const float* gtb = g_gt + (size_t)b * HWn;
    unsigned* ew = g_edgew + (size_t)b * NWRD;
    unsigned* bw = g_blkw  + (size_t)b * NWRD;

    auto loadrow = [&](int y) -> R6v {
        R6v t;
        const bool rv = ((unsigned)y < (unsigned)Hn);
        float4 g = make_float4(0.f, 0.f, 0.f, 0.f);
        if (rv) g = *(const float4*)(gtb + (size_t)y * Wn + x0v);
        float lf = __shfl_up_sync(0xffffffffu, g.w, 1);
        float rt = __shfl_down_sync(0xffffffffu, g.x, 1);
        if (lane == 0)  lf = (rv && s > 0)       ? __ldg(gtb + (size_t)y * Wn + x0v - 1) : 0.f;
        if (lane == 31) rt = (rv && s < SPN - 1) ? __ldg(gtb + (size_t)y * Wn + x0v + 4) : 0.f;
        t.v[0] = lf; t.v[1] = g.x; t.v[2] = g.y; t.v[3] = g.z; t.v[4] = g.w; t.v[5] = rt;
        return t;
    };

    R6v rA = loadrow(yB - 1);
    R6v rB = loadrow(yB);

    #pragma unroll
    for (int t8 = 0; t8 < 8; t8++) {
        const int y = yB + t8;           // always 0..1079 (135*8 == 1080)
        R6v n = loadrow(y + 1);
        const bool r8 = (y & 7) == 0;

        unsigned nibE = 0u, nibB = 0u;
        #pragma unroll
        for (int i = 0; i < 4; i++) {
            float gx = (rA.v[i+2] - rA.v[i]) + 2.f * (rB.v[i+2] - rB.v[i]) + (n.v[i+2] - n.v[i]);
            float gy = (n.v[i] - rA.v[i]) + 2.f * (n.v[i+1] - rA.v[i+1]) + (n.v[i+2] - rA.v[i+2]);
            bool e = sqrtf(gx * gx + gy * gy) > 0.15f;
            // col = s*128 + 4*lane + i; col%8==0 iff i==0 && lane even
            float bv = ((i == 0) && ((lane & 1) == 0)) ? fabsf(gx) : 0.f;
            if (r8) bv = fmaxf(bv, fabsf(gy));
            bool bl = bv > 0.05f;
            nibE |= (unsigned)e  << i;
            nibB |= (unsigned)bl << i;
        }
        unsigned ve = nibE << (4 * (lane & 7));
        unsigned vb = nibB << (4 * (lane & 7));
        ve |= __shfl_xor_sync(0xffffffffu, ve, 1);
        vb |= __shfl_xor_sync(0xffffffffu, vb, 1);
        ve |= __shfl_xor_sync(0xffffffffu, ve, 2);
        vb |= __shfl_xor_sync(0xffffffffu, vb, 2);
        ve |= __shfl_xor_sync(0xffffffffu, ve, 4);
        vb |= __shfl_xor_sync(0xffffffffu, vb, 4);
        if ((lane & 7) == 0) {
            const int w = s * 4 + (lane >> 3);
            ew[y * NSPAN + w] = ve;
            bw[y * NSPAN + w] = vb;
        }
        rA = rB; rB = n;
    }
}

// ---------------- K3: pure streaming output kernel (no smem, no barriers) --
// block (32,8); thread = col gx, rows yb..yb+3. grid (60, 34, 4).
__global__ __launch_bounds__(256) void k3_out(float* __restrict__ diag) {
    const int lane = threadIdx.x;
    const int ty   = threadIdx.y;
    const int s    = blockIdx.x;
    const int b    = blockIdx.z;
    const int yb   = blockIdx.y * 32 + ty * 4;
    const int gx   = s * 32 + lane;

    const __half2* hqb = g_hrt + (size_t)b * HWn;
    const __half2* dcp = g_dc  + (size_t)b * HWn;
    const unsigned* ew = g_edgew + (size_t)b * NWRD;
    const unsigned* bw = g_blkw  + (size_t)b * NWRD;
    float* o_an = diag + ((size_t)b * 5 + 0) * HWn;
    float* o_cm = diag + ((size_t)b * 5 + 1) * HWn;
    float* o_ss = diag + ((size_t)b * 5 + 2) * HWn;
    float* o_bl = diag + ((size_t)b * 5 + 3) * HWn;
    float* o_ri = diag + ((size_t)b * 5 + 4) * HWn;

    // ---- hrt vertical windows: rows yb-3 .. yb+6 ----
    float2 h[10];
    #pragma unroll
    for (int k = 0; k < 10; k++) {
        int y = yb - 3 + k;
        h[k] = ((unsigned)y < (unsigned)Hn)
             ? __half22float2(__ldg(hqb + (size_t)y * Wn + gx))
             : make_float2(0.f, 0.f);
    }
    float mur[4], mut[4];
    #pragma unroll
    for (int q = 0; q < 4; q++) {
        float sr = 0.f, st = 0.f;
        #pragma unroll
        for (int k = 0; k < 7; k++) { sr += h[q + k].x; st += h[q + k].y; }
        mur[q] = sr; mut[q] = st;
    }

    // ---- dc for the 4 output pixels ----
    __half2 pdc[4];
    #pragma unroll
    for (int r = 0; r < 4; r++) {
        int y = yb + r;
        pdc[r] = (y < Hn) ? __ldg(dcp + (size_t)y * Wn + gx) : __half2(__float2half2_rn(0.f));
    }

    // ---- gather mask words via lane-split load + shuffles ----
    unsigned v = 0u;
    {
        const int r = lane & 7;
        const int row = yb - 2 + r;
        const bool okr = ((unsigned)row < (unsigned)Hn);
        if (lane < 8) {
            if (okr) v = __ldg(ew + row * NSPAN + s);
        } else if (lane < 16) {
            if (okr && s > 0) v = __ldg(ew + row * NSPAN + s - 1);
        } else if (lane < 24) {
            if (okr && s < NSPAN - 1) v = __ldg(ew + row * NSPAN + s + 1);
        } else {
            const int q = lane - 24;
            const int row2 = yb + q;
            if (q < 4 && row2 < Hn) v = __ldg(bw + row2 * NSPAN + s);
        }
    }
    unsigned ec[8], hd[8], bkw[4];
    #pragma unroll
    for (int r = 0; r < 8; r++) {
        unsigned cw = __shfl_sync(0xffffffffu, v, r);
        unsigned pw = __shfl_sync(0xffffffffu, v, 8 + r);
        unsigned nw = __shfl_sync(0xffffffffu, v, 16 + r);
        ec[r] = cw;
        hd[r] = cw | (cw << 1) | (cw << 2) | (cw >> 1) | (cw >> 2)
              | (pw >> 30) | (pw >> 31) | (nw << 30) | (nw << 31);
    }
    #pragma unroll
    for (int q = 0; q < 4; q++) bkw[q] = __shfl_sync(0xffffffffu, v, 24 + q);

    const float invd  = g_invd;
    const float invcd = g_invcd;

    #pragma unroll
    for (int q = 0; q < 4; q++) {
        const int y = yb + q;
        if (y >= Hn) break;

        unsigned dw = hd[q] | hd[q + 1] | hd[q + 2] | hd[q + 3] | hd[q + 4];
        float dil = (float)((dw        >> lane) & 1u);
        float e   = (float)((ec[q + 2] >> lane) & 1u);
        float bk  = (float)((bkw[q]    >> lane) & 1u);

        float mu_r = mur[q] * (1.f / 49.f), mu_t = mut[q] * (1.f / 49.f);
        float ssim = (2.f * mu_r * mu_t + 1e-4f) / (mu_r * mu_r + mu_t * mu_t + 1e-4f);

        float2 dc = __half22float2(pdc[q]);
        float an  = dc.x * invd;
        float cm  = dc.y * invcd;
        float ring = fmaxf(dil - e, 0.f) * an;

        const size_t idx = (size_t)y * Wn + gx;
        o_an[idx] = an;
        o_cm[idx] = cm;
        o_ss[idx] = ssim;
        o_bl[idx] = bk;
        o_ri[idx] = ring;
    }
}

// ---------------- launch ---------------------------------------------------
extern "C" void kernel_launch(void* const* d_in, const int* in_sizes, int n_in,
                              void* d_out, int out_size) {
    const float* ref = (const float*)d_in[0];
    const float* tgt = (const float*)d_in[1];
    float* out = (float*)d_out;

    k0_init<<<1, 32>>>();

    dim3 g1(Hn, Bn);
    k1_point<<<g1, 480>>>(ref, tgt);

    k2_score<<<1, 32>>>(out);

    k2b_edge<<<(SPN * 135 * Bn + 7) / 8, 256>>>();

    dim3 g3(NSPAN, (Hn + 31) / 32, Bn);
    dim3 b3(32, 8);
    k3_out<<<g3, b3>>>(out + Bn);
}

// round 11
// speedup vs baseline: 2.0291x; 1.0034x over previous
#include <cuda_runtime.h>
#include <cuda_fp16.h>
#include <math.h>

#define Bn 4
#define Hn 1080
#define Wn 1920
#define HWn (Hn * Wn)   // 2073600
#define NSPAN 60        // 1920 / 32 (bit-words per row)
#define NWRD  (Hn * NSPAN)
#define SPN   15        // 1920 / 128 (k2b warp spans)
#define KCH   4         // k2b rows per warp
#define NCHK  (Hn / KCH)  // 270

// ---------------- scratch (no runtime allocation allowed) ----------------
__device__ __align__(16) __half2 g_dc [Bn * HWn];   // (sqrt-diff, color-diff) fp16
__device__ __align__(16) float   g_gt [Bn * HWn];   // tgt gray fp32
__device__ __align__(16) __half2 g_hrt[Bn * HWn];   // (hsum7_ref, hsum7_tgt) fp16
__device__ __align__(16) unsigned g_edgew[Bn * NWRD];  // edge bits, 1/px
__device__ __align__(16) unsigned g_blkw [Bn * NWRD];  // blocking bits, 1/px
__device__ int   g_maxd_i;
__device__ int   g_maxcd_i;
__device__ float g_sum[Bn];
__device__ float g_invd, g_invcd;

static __forceinline__ __device__ unsigned h2u(__half2 h) {
    return *reinterpret_cast<unsigned*>(&h);
}

// ---------------- K0: zero reduction scalars ------------------------------
__global__ void k0_init() {
    int t = threadIdx.x;
    if (t == 0) g_maxd_i = 0;
    if (t == 1) g_maxcd_i = 0;
    if (t >= 2 && t < 2 + Bn) g_sum[t - 2] = 0.f;
}

// ---------------- K1: one row per block; pointwise + horizontal 7-sums ---
__global__ __launch_bounds__(480) void k1_point(const float* __restrict__ ref,
                                                const float* __restrict__ tgt) {
    const int y = blockIdx.x;
    const int b = blockIdx.y;
    const int t = threadIdx.x;           // 0..479

    __shared__ __align__(16) float srow_r[1928];   // 4 zero pad each side
    __shared__ __align__(16) float srow_t[1928];
    __shared__ float smx[15], smc[15], sms[15];

    if (t < 4) {
        srow_r[t] = 0.f; srow_t[t] = 0.f;
        srow_r[1924 + t] = 0.f; srow_t[1924 + t] = 0.f;
    }

    const size_t rowpx = (size_t)y * Wn + 4 * t;
    const int v = (int)(rowpx >> 2);

    const float4 r0 = ((const float4*)(ref + (size_t)(b * 3 + 0) * HWn))[v];
    const float4 r1 = ((const float4*)(ref + (size_t)(b * 3 + 1) * HWn))[v];
    const float4 r2 = ((const float4*)(ref + (size_t)(b * 3 + 2) * HWn))[v];
    const float4 t0 = ((const float4*)(tgt + (size_t)(b * 3 + 0) * HWn))[v];
    const float4 t1 = ((const float4*)(tgt + (size_t)(b * 3 + 1) * HWn))[v];
    const float4 t2 = ((const float4*)(tgt + (size_t)(b * 3 + 2) * HWn))[v];

    float4 D, C, GR, GT;
    float lmaxd = 0.f, lmaxcd = 0.f, lsum = 0.f;

#define LANE(c)                                                               \
    {                                                                         \
        float d0 = r0.c - t0.c, d1 = r1.c - t1.c, d2 = r2.c - t2.c;           \
        float df = sqrtf(d0 * d0 + d1 * d1 + d2 * d2);                        \
        float cd = (fabsf(d0) + fabsf(d1) + fabsf(d2)) * (1.f / 3.f);         \
        D.c = df; C.c = cd;                                                   \
        GR.c = 0.299f * r0.c + 0.587f * r1.c + 0.114f * r2.c;                 \
        GT.c = 0.299f * t0.c + 0.587f * t1.c + 0.114f * t2.c;                 \
        lmaxd = fmaxf(lmaxd, df); lmaxcd = fmaxf(lmaxcd, cd);                 \
        lsum += df;                                                           \
    }
    LANE(x) LANE(y) LANE(z) LANE(w)
#undef LANE

    uint4 dc;
    dc.x = h2u(__floats2half2_rn(D.x, C.x));
    dc.y = h2u(__floats2half2_rn(D.y, C.y));
    dc.z = h2u(__floats2half2_rn(D.z, C.z));
    dc.w = h2u(__floats2half2_rn(D.w, C.w));
    ((uint4*)(g_dc + (size_t)b * HWn))[v] = dc;
    ((float4*)(g_gt + (size_t)b * HWn))[v] = GT;

    *(float4*)&srow_r[4 + 4 * t] = GR;
    *(float4*)&srow_t[4 + 4 * t] = GT;

    #pragma unroll
    for (int o = 16; o > 0; o >>= 1) {
        lmaxd  = fmaxf(lmaxd,  __shfl_xor_sync(0xffffffffu, lmaxd,  o));
        lmaxcd = fmaxf(lmaxcd, __shfl_xor_sync(0xffffffffu, lmaxcd, o));
        lsum  +=               __shfl_xor_sync(0xffffffffu, lsum,   o);
    }
    const int lane = t & 31, wid = t >> 5;
    if (lane == 0) { smx[wid] = lmaxd; smc[wid] = lmaxcd; sms[wid] = lsum; }
    __syncthreads();
    if (t == 0) {
        float mx = smx[0], mc = smc[0], s = sms[0];
        #pragma unroll
        for (int i = 1; i < 15; i++) {
            mx = fmaxf(mx, smx[i]); mc = fmaxf(mc, smc[i]); s += sms[i];
        }
        atomicMax(&g_maxd_i,  __float_as_int(mx));
        atomicMax(&g_maxcd_i, __float_as_int(mc));
        atomicAdd(&g_sum[b], s);
    }

    const float* ar = srow_r + 4 * t;
    const float* at = srow_t + 4 * t;
    float4 A0 = *(const float4*)(ar), A1 = *(const float4*)(ar + 4), A2 = *(const float4*)(ar + 8);
    float4 B0 = *(const float4*)(at), B1 = *(const float4*)(at + 4), B2 = *(const float4*)(at + 8);
    float a[12] = {A0.x,A0.y,A0.z,A0.w, A1.x,A1.y,A1.z,A1.w, A2.x,A2.y,A2.z,A2.w};
    float c[12] = {B0.x,B0.y,B0.z,B0.w, B1.x,B1.y,B1.z,B1.w, B2.x,B2.y,B2.z,B2.w};

    float hr0 = a[1]+a[2]+a[3]+a[4]+a[5]+a[6]+a[7];
    float ht0 = c[1]+c[2]+c[3]+c[4]+c[5]+c[6]+c[7];
    float hr1 = hr0 + a[8] - a[1], ht1 = ht0 + c[8] - c[1];
    float hr2 = hr1 + a[9] - a[2], ht2 = ht1 + c[9] - c[2];
    float hr3 = hr2 + a[10] - a[3], ht3 = ht2 + c[10] - c[3];

    uint4 hq;
    hq.x = h2u(__floats2half2_rn(hr0, ht0));
    hq.y = h2u(__floats2half2_rn(hr1, ht1));
    hq.z = h2u(__floats2half2_rn(hr2, ht2));
    hq.w = h2u(__floats2half2_rn(hr3, ht3));
    ((uint4*)(g_hrt + (size_t)b * HWn))[v] = hq;
}

// ---------------- K2: score + inverse normalizers ------------------------
__global__ void k2_score(float* __restrict__ out) {
    const int t = threadIdx.x;
    const float invd  = 1.f / (__int_as_float(g_maxd_i)  + 1e-12f);
    const float invcd = 1.f / (__int_as_float(g_maxcd_i) + 1e-12f);
    if (t == 0) { g_invd = invd; g_invcd = invcd; }
    if (t < Bn) {
        float m = g_sum[t] * (1.f / (float)HWn) * invd;
        out[t] = fminf(fmaxf(1.f - m, 0.f), 1.f);
    }
}

// ---------------- K2b: vectorized Sobel -> edge/blocking bit-words ---------
// Warp = 128-col span (float4 per thread) x KCH=4 rows sliding. 15 spans x
// 270 chunks x 4 batches = 16200 warps = 2025 blocks.
struct R6v { float v[6]; };   // [l, x, y, z, w, r]

__global__ __launch_bounds__(256) void k2b_edge() {
    const int lane = threadIdx.x & 31;
    const int task = blockIdx.x * 8 + (threadIdx.x >> 5);
    if (task >= SPN * NCHK * Bn) return;
    const int s    = task % SPN;
    const int rem  = task / SPN;
    const int chnk = rem % NCHK;
    const int b    = rem / NCHK;
    const int yB   = chnk * KCH;
    const int x0v  = s * 128 + lane * 4;

    const float* gtb = g_gt + (size_t)b * HWn;
    unsigned* ew = g_edgew + (size_t)b * NWRD;
    unsigned* bw = g_blkw  + (size_t)b * NWRD;

    auto loadrow = [&](int y) -> R6v {
        R6v t;
        const bool rv = ((unsigned)y < (unsigned)Hn);
        float4 g = make_float4(0.f, 0.f, 0.f, 0.f);
        if (rv) g = *(const float4*)(gtb + (size_t)y * Wn + x0v);
        float lf = __shfl_up_sync(0xffffffffu, g.w, 1);
        float rt = __shfl_down_sync(0xffffffffu, g.x, 1);
        if (lane == 0)  lf = (rv && s > 0)       ? __ldg(gtb + (size_t)y * Wn + x0v - 1) : 0.f;
        if (lane == 31) rt = (rv && s < SPN - 1) ? __ldg(gtb + (size_t)y * Wn + x0v + 4) : 0.f;
        t.v[0] = lf; t.v[1] = g.x; t.v[2] = g.y; t.v[3] = g.z; t.v[4] = g.w; t.v[5] = rt;
        return t;
    };

    R6v rA = loadrow(yB - 1);
    R6v rB = loadrow(yB);

    #pragma unroll
    for (int t8 = 0; t8 < KCH; t8++) {
        const int y = yB + t8;           // always 0..1079 (NCHK*KCH == 1080)
        R6v n = loadrow(y + 1);
        const bool r8 = (y & 7) == 0;

        unsigned nibE = 0u, nibB = 0u;
        #pragma unroll
        for (int i = 0; i < 4; i++) {
            float gx = (rA.v[i+2] - rA.v[i]) + 2.f * (rB.v[i+2] - rB.v[i]) + (n.v[i+2] - n.v[i]);
            float gy = (n.v[i] - rA.v[i]) + 2.f * (n.v[i+1] - rA.v[i+1]) + (n.v[i+2] - rA.v[i+2]);
            bool e = sqrtf(gx * gx + gy * gy) > 0.15f;
            // col = s*128 + 4*lane + i; col%8==0 iff i==0 && lane even
            float bv = ((i == 0) && ((lane & 1) == 0)) ? fabsf(gx) : 0.f;
            if (r8) bv = fmaxf(bv, fabsf(gy));
            bool bl = bv > 0.05f;
            nibE |= (unsigned)e  << i;
            nibB |= (unsigned)bl << i;
        }
        unsigned ve = nibE << (4 * (lane & 7));
        unsigned vb = nibB << (4 * (lane & 7));
        ve |= __shfl_xor_sync(0xffffffffu, ve, 1);
        vb |= __shfl_xor_sync(0xffffffffu, vb, 1);
        ve |= __shfl_xor_sync(0xffffffffu, ve, 2);
        vb |= __shfl_xor_sync(0xffffffffu, vb, 2);
        ve |= __shfl_xor_sync(0xffffffffu, ve, 4);
        vb |= __shfl_xor_sync(0xffffffffu, vb, 4);
        if ((lane & 7) == 0) {
            const int w = s * 4 + (lane >> 3);
            ew[y * NSPAN + w] = ve;
            bw[y * NSPAN + w] = vb;
        }
        rA = rB; rB = n;
    }
}

// ---------------- K3: pure streaming output kernel (no smem, no barriers) --
// block (32,8); thread = col gx, rows yb..yb+3. grid (60, 34, 4).
__global__ __launch_bounds__(256) void k3_out(float* __restrict__ diag) {
    const int lane = threadIdx.x;
    const int ty   = threadIdx.y;
    const int s    = blockIdx.x;
    const int b    = blockIdx.z;
    const int yb   = blockIdx.y * 32 + ty * 4;
    const int gx   = s * 32 + lane;

    const __half2* hqb = g_hrt + (size_t)b * HWn;
    const __half2* dcp = g_dc  + (size_t)b * HWn;
    const unsigned* ew = g_edgew + (size_t)b * NWRD;
    const unsigned* bw = g_blkw  + (size_t)b * NWRD;
    float* o_an = diag + ((size_t)b * 5 + 0) * HWn;
    float* o_cm = diag + ((size_t)b * 5 + 1) * HWn;
    float* o_ss = diag + ((size_t)b * 5 + 2) * HWn;
    float* o_bl = diag + ((size_t)b * 5 + 3) * HWn;
    float* o_ri = diag + ((size_t)b * 5 + 4) * HWn;

    // ---- hrt vertical windows: rows yb-3 .. yb+6 ----
    float2 h[10];
    #pragma unroll
    for (int k = 0; k < 10; k++) {
        int y = yb - 3 + k;
        h[k] = ((unsigned)y < (unsigned)Hn)
             ? __half22float2(__ldg(hqb + (size_t)y * Wn + gx))
             : make_float2(0.f, 0.f);
    }
    float mur[4], mut[4];
    #pragma unroll
    for (int q = 0; q < 4; q++) {
        float sr = 0.f, st = 0.f;
        #pragma unroll
        for (int k = 0; k < 7; k++) { sr += h[q + k].x; st += h[q + k].y; }
        mur[q] = sr; mut[q] = st;
    }

    // ---- dc for the 4 output pixels ----
    __half2 pdc[4];
    #pragma unroll
    for (int r = 0; r < 4; r++) {
        int y = yb + r;
        pdc[r] = (y < Hn) ? __ldg(dcp + (size_t)y * Wn + gx) : __half2(__float2half2_rn(0.f));
    }

    // ---- gather mask words via lane-split load + shuffles ----
    unsigned v = 0u;
    {
        const int r = lane & 7;
        const int row = yb - 2 + r;
        const bool okr = ((unsigned)row < (unsigned)Hn);
        if (lane < 8) {
            if (okr) v = __ldg(ew + row * NSPAN + s);
        } else if (lane < 16) {
            if (okr && s > 0) v = __ldg(ew + row * NSPAN + s - 1);
        } else if (lane < 24) {
            if (okr && s < NSPAN - 1) v = __ldg(ew + row * NSPAN + s + 1);
        } else {
            const int q = lane - 24;
            const int row2 = yb + q;
            if (q < 4 && row2 < Hn) v = __ldg(bw + row2 * NSPAN + s);
        }
    }
    unsigned ec[8], hd[8], bkw[4];
    #pragma unroll
    for (int r = 0; r < 8; r++) {
        unsigned cw = __shfl_sync(0xffffffffu, v, r);
        unsigned pw = __shfl_sync(0xffffffffu, v, 8 + r);
        unsigned nw = __shfl_sync(0xffffffffu, v, 16 + r);
        ec[r] = cw;
        hd[r] = cw | (cw << 1) | (cw << 2) | (cw >> 1) | (cw >> 2)
              | (pw >> 30) | (pw >> 31) | (nw << 30) | (nw << 31);
    }
    #pragma unroll
    for (int q = 0; q < 4; q++) bkw[q] = __shfl_sync(0xffffffffu, v, 24 + q);

    const float invd  = g_invd;
    const float invcd = g_invcd;

    #pragma unroll
    for (int q = 0; q < 4; q++) {
        const int y = yb + q;
        if (y >= Hn) break;

        unsigned dw = hd[q] | hd[q + 1] | hd[q + 2] | hd[q + 3] | hd[q + 4];
        float dil = (float)((dw        >> lane) & 1u);
        float e   = (float)((ec[q + 2] >> lane) & 1u);
        float bk  = (float)((bkw[q]    >> lane) & 1u);

        float mu_r = mur[q] * (1.f / 49.f), mu_t = mut[q] * (1.f / 49.f);
        float ssim = (2.f * mu_r * mu_t + 1e-4f) / (mu_r * mu_r + mu_t * mu_t + 1e-4f);

        float2 dc = __half22float2(pdc[q]);
        float an  = dc.x * invd;
        float cm  = dc.y * invcd;
        float ring = fmaxf(dil - e, 0.f) * an;

        const size_t idx = (size_t)y * Wn + gx;
        o_an[idx] = an;
        o_cm[idx] = cm;
        o_ss[idx] = ssim;
        o_bl[idx] = bk;
        o_ri[idx] = ring;
    }
}

// ---------------- launch ---------------------------------------------------
extern "C" void kernel_launch(void* const* d_in, const int* in_sizes, int n_in,
                              void* d_out, int out_size) {
    const float* ref = (const float*)d_in[0];
    const float* tgt = (const float*)d_in[1];
    float* out = (float*)d_out;

    k0_init<<<1, 32>>>();

    dim3 g1(Hn, Bn);
    k1_point<<<g1, 480>>>(ref, tgt);

    k2_score<<<1, 32>>>(out);

    k2b_edge<<<(SPN * NCHK * Bn + 7) / 8, 256>>>();

    dim3 g3(NSPAN, (Hn + 31) / 32, Bn);
    dim3 b3(32, 8);
    k3_out<<<g3, b3>>>(out + Bn);
}